// round 2
// baseline (speedup 1.0000x reference)
#include <cuda_runtime.h>

#define NNODES 100000
#define NEDGES 800000
#define DH 96
#define C4 (DH / 4)   // 24 float4 chunks per row

// ---- scratch (static device allocations are the sanctioned workaround) ----
__device__ float g_H[NNODES * DH];     // GEMM output (per layer)
__device__ float g_AGG[NNODES * DH];   // aggregation accumulator
__device__ float g_dis[NNODES];        // deg, then rsqrt(deg)

// ============================ norm ============================

__global__ void deg_init_kernel() {
    int i = blockIdx.x * blockDim.x + threadIdx.x;
    if (i < NNODES) g_dis[i] = 1.0f;   // self-loop
}

__global__ void deg_count_kernel(const int* __restrict__ ei) {
    int e = blockIdx.x * blockDim.x + threadIdx.x;
    if (e < NEDGES) atomicAdd(&g_dis[ei[NEDGES + e]], 1.0f);
}

__global__ void deg_rsqrt_kernel() {
    int i = blockIdx.x * blockDim.x + threadIdx.x;
    if (i < NNODES) g_dis[i] = rsqrtf(g_dis[i]);
}

// ============================ GEMM ============================
// out[n, 96] = A[n, 96] @ W[96, 96]
// If fuse != 0, the A operand is transformed elementwise on load:
//   a = relu(a + bias[k])   (layer-2 consumes relu(AGG1 + b1))
// BM=64, BN=96 (full), BK=48 (2 k-tiles), 192 threads, thread tile 4x8.

#define BM 64
#define BK 48
#define TM 4
#define TN 8

__global__ void __launch_bounds__(192)
gemm96_kernel(const float* __restrict__ A, const float* __restrict__ W,
              const float* __restrict__ bias, float* __restrict__ out,
              int nrows, int fuse) {
    __shared__ float As[BM][BK + 1];   // +1 pad: spread ty accesses over banks
    __shared__ float Bs[BK][DH];

    const int tid = threadIdx.x;
    const int tx = tid % 12;           // col group: cols [tx*8, tx*8+8)
    const int ty = tid / 12;           // row group: rows [ty*4, ty*4+4)
    const int row0 = blockIdx.x * BM;

    float acc[TM][TN];
#pragma unroll
    for (int i = 0; i < TM; i++)
#pragma unroll
        for (int j = 0; j < TN; j++) acc[i][j] = 0.0f;

#pragma unroll
    for (int kt = 0; kt < 2; kt++) {
        const int kbase = kt * BK;

        // load A tile [BM x BK] (coalesced along k)
#pragma unroll
        for (int l = tid; l < BM * BK; l += 192) {
            int m = l / BK, k = l % BK;
            int row = row0 + m;
            float v = 0.0f;
            if (row < nrows) {
                v = A[row * DH + kbase + k];
                if (fuse) v = fmaxf(v + bias[kbase + k], 0.0f);
            }
            As[m][k] = v;
        }
        // load W tile [BK x 96] (fully coalesced)
#pragma unroll
        for (int l = tid; l < BK * DH; l += 192) {
            int kk = l / DH, n = l % DH;
            Bs[kk][n] = W[(kbase + kk) * DH + n];
        }
        __syncthreads();

#pragma unroll 8
        for (int k = 0; k < BK; k++) {
            float a[TM];
#pragma unroll
            for (int i = 0; i < TM; i++) a[i] = As[ty * TM + i][k];
            float4 b0 = *(const float4*)&Bs[k][tx * TN];
            float4 b1 = *(const float4*)&Bs[k][tx * TN + 4];
#pragma unroll
            for (int i = 0; i < TM; i++) {
                acc[i][0] = fmaf(a[i], b0.x, acc[i][0]);
                acc[i][1] = fmaf(a[i], b0.y, acc[i][1]);
                acc[i][2] = fmaf(a[i], b0.z, acc[i][2]);
                acc[i][3] = fmaf(a[i], b0.w, acc[i][3]);
                acc[i][4] = fmaf(a[i], b1.x, acc[i][4]);
                acc[i][5] = fmaf(a[i], b1.y, acc[i][5]);
                acc[i][6] = fmaf(a[i], b1.z, acc[i][6]);
                acc[i][7] = fmaf(a[i], b1.w, acc[i][7]);
            }
        }
        __syncthreads();
    }

#pragma unroll
    for (int i = 0; i < TM; i++) {
        int row = row0 + ty * TM + i;
        if (row < nrows) {
            float4 o0 = make_float4(acc[i][0], acc[i][1], acc[i][2], acc[i][3]);
            float4 o1 = make_float4(acc[i][4], acc[i][5], acc[i][6], acc[i][7]);
            *(float4*)&out[row * DH + tx * TN]     = o0;
            *(float4*)&out[row * DH + tx * TN + 4] = o1;
        }
    }
}

// ============================ aggregation ============================

// AGG[i] = H[i] * dis[i]^2   (self-loop term; also initializes AGG)
__global__ void agg_init_kernel() {
    int idx = blockIdx.x * blockDim.x + threadIdx.x;   // float4 index
    int node = idx / C4;
    if (node >= NNODES) return;
    float d = g_dis[node];
    float s = d * d;
    float4 v = ((const float4*)g_H)[idx];
    v.x *= s; v.y *= s; v.z *= s; v.w *= s;
    ((float4*)g_AGG)[idx] = v;
}

// AGG[dst] += H[src] * dis[src]*dis[dst], one thread per (edge, float4 chunk)
__global__ void scatter_kernel(const int* __restrict__ ei) {
    int idx = blockIdx.x * blockDim.x + threadIdx.x;
    int e = idx / C4;
    int c = idx - e * C4;
    if (e >= NEDGES) return;
    int s = __ldg(&ei[e]);
    int d = __ldg(&ei[NEDGES + e]);
    float nrm = __ldg(&g_dis[s]) * __ldg(&g_dis[d]);
    float4 v = __ldg((const float4*)&g_H[s * DH] + c);
    v.x *= nrm; v.y *= nrm; v.z *= nrm; v.w *= nrm;
    float* addr = &g_AGG[d * DH + 4 * c];
    asm volatile("red.global.add.v4.f32 [%0], {%1, %2, %3, %4};"
                 :: "l"(addr), "f"(v.x), "f"(v.y), "f"(v.z), "f"(v.w)
                 : "memory");
}

// out = relu(AGG + b2)
__global__ void final_kernel(const float* __restrict__ b2, float* __restrict__ out) {
    int idx = blockIdx.x * blockDim.x + threadIdx.x;   // float4 index
    int node = idx / C4;
    int c = idx - node * C4;
    if (node >= NNODES) return;
    float4 v = ((const float4*)g_AGG)[idx];
    float4 b = __ldg((const float4*)b2 + c);
    v.x = fmaxf(v.x + b.x, 0.0f);
    v.y = fmaxf(v.y + b.y, 0.0f);
    v.z = fmaxf(v.z + b.z, 0.0f);
    v.w = fmaxf(v.w + b.w, 0.0f);
    ((float4*)out)[idx] = v;
}

// ============================ launch ============================

extern "C" void kernel_launch(void* const* d_in, const int* in_sizes, int n_in,
                              void* d_out, int out_size) {
    const float* x  = (const float*)d_in[0];
    const int*   ei = (const int*)d_in[1];
    const float* W1 = (const float*)d_in[2];
    const float* b1 = (const float*)d_in[3];
    const float* W2 = (const float*)d_in[4];
    const float* b2 = (const float*)d_in[5];
    float* out = (float*)d_out;

    void *pH_v, *pAGG_v;
    cudaGetSymbolAddress(&pH_v, g_H);
    cudaGetSymbolAddress(&pAGG_v, g_AGG);
    float* pH   = (float*)pH_v;
    float* pAGG = (float*)pAGG_v;

    const int T = 256;
    int nBlkN    = (NNODES + T - 1) / T;
    int nBlkE    = (NEDGES + T - 1) / T;
    int nBlkRow4 = (NNODES * C4 + T - 1) / T;     // node x float4-chunk grid
    int nBlkEdg4 = (NEDGES * C4 + T - 1) / T;     // edge x float4-chunk grid
    int nBlkGemm = (NNODES + BM - 1) / BM;

    // norm
    deg_init_kernel<<<nBlkN, T>>>();
    deg_count_kernel<<<nBlkE, T>>>(ei);
    deg_rsqrt_kernel<<<nBlkN, T>>>();

    // layer 1: H = x @ W1 ; AGG = self-loop + scatter
    gemm96_kernel<<<nBlkGemm, 192>>>(x, W1, nullptr, pH, NNODES, 0);
    agg_init_kernel<<<nBlkRow4, T>>>();
    scatter_kernel<<<nBlkEdg4, T>>>(ei);

    // layer 2: H2 = relu(AGG + b1) @ W2 ; AGG = self-loop + scatter
    gemm96_kernel<<<nBlkGemm, 192>>>(pAGG, W2, b1, pH, NNODES, 1);
    agg_init_kernel<<<nBlkRow4, T>>>();
    scatter_kernel<<<nBlkEdg4, T>>>(ei);

    // out = relu(AGG + b2)
    final_kernel<<<nBlkRow4, T>>>(b2, out);
}

// round 3
// speedup vs baseline: 1.3729x; 1.3729x over previous
#include <cuda_runtime.h>

#define NNODES 100000
#define NEDGES 800000
#define DH 96
#define C4 (DH / 4)   // 24 float4 chunks per row

// ---- scratch (static device allocations are the sanctioned workaround) ----
__device__ float g_H[NNODES * DH];     // GEMM output (per layer)
__device__ float g_AGG[NNODES * DH];   // aggregation accumulator
__device__ float g_dis[NNODES];        // deg, then rsqrt(deg)

// ============================ f32x2 helpers ============================

__device__ __forceinline__ unsigned long long pack2(float x) {
    unsigned long long r;
    asm("mov.b64 %0, {%1, %1};" : "=l"(r) : "f"(x));
    return r;
}
__device__ __forceinline__ void ffma2(unsigned long long& d,
                                      unsigned long long a,
                                      unsigned long long b) {
    asm("fma.rn.f32x2 %0, %1, %2, %0;" : "+l"(d) : "l"(a), "l"(b));
}
__device__ __forceinline__ void unpack2(unsigned long long v, float& lo, float& hi) {
    asm("mov.b64 {%0, %1}, %2;" : "=f"(lo), "=f"(hi) : "l"(v));
}

// ============================ norm ============================

__global__ void deg_init_kernel() {
    int i = blockIdx.x * blockDim.x + threadIdx.x;
    if (i < NNODES) g_dis[i] = 1.0f;   // self-loop
}

__global__ void deg_count_kernel(const int* __restrict__ ei) {
    int e = blockIdx.x * blockDim.x + threadIdx.x;
    if (e < NEDGES) atomicAdd(&g_dis[ei[NEDGES + e]], 1.0f);
}

__global__ void deg_rsqrt_kernel() {
    int i = blockIdx.x * blockDim.x + threadIdx.x;
    if (i < NNODES) g_dis[i] = rsqrtf(g_dis[i]);
}

// ============================ GEMM (f32x2) ============================
// outH[n, 96] = A'[n, 96] @ W[96, 96]  where A' = fuse ? relu(A + bias) : A
// Also writes agg[n] = outH[n] * dis[n]^2 (self-loop init, fused epilogue).
// BM=128 rows/block, BK=32, 256 threads. Thread tile 8 (M) x 6 (N),
// accumulators paired over M as f32x2 -> 24 FFMA2 per thread per k.

#define GBM 128
#define GBK 32
#define APITCH 130   // even (LDS.64-aligned), 130 % 32 == 2 -> only 2-way STS conflicts

__global__ void __launch_bounds__(256, 2)
gemm96_f32x2_kernel(const float* __restrict__ A, const float* __restrict__ W,
                    const float* __restrict__ bias, float* __restrict__ outH,
                    float* __restrict__ agg, int fuse) {
    __shared__ float AsT[GBK][APITCH];   // [k][m] transposed A tile
    __shared__ float Ws[GBK][DH];        // [k][n]

    const int tid = threadIdx.x;
    const int tx = tid & 15;             // n-group: cols [tx*6, tx*6+6)
    const int ty = tid >> 4;             // m-group: rows [ty*8, ty*8+8)
    const int row0 = blockIdx.x * GBM;

    unsigned long long acc[4][6];
#pragma unroll
    for (int p = 0; p < 4; p++)
#pragma unroll
        for (int j = 0; j < 6; j++) acc[p][j] = 0ull;

#pragma unroll 1
    for (int kt = 0; kt < 3; kt++) {
        const int kb = kt * GBK;

        // ---- A tile load (transposed into AsT), 16 elems/thread via float4 ----
        {
            int r  = tid >> 1;                 // 0..127
            int kq = (tid & 1) * 16;           // 0 or 16
            int grow = row0 + r;
            float vs[16];
            if (grow < NNODES) {
                const float4* ap = (const float4*)(A + (size_t)grow * DH + kb + kq);
                float4 v0 = ap[0], v1 = ap[1], v2 = ap[2], v3 = ap[3];
                vs[0]=v0.x; vs[1]=v0.y; vs[2]=v0.z; vs[3]=v0.w;
                vs[4]=v1.x; vs[5]=v1.y; vs[6]=v1.z; vs[7]=v1.w;
                vs[8]=v2.x; vs[9]=v2.y; vs[10]=v2.z; vs[11]=v2.w;
                vs[12]=v3.x; vs[13]=v3.y; vs[14]=v3.z; vs[15]=v3.w;
            } else {
#pragma unroll
                for (int j = 0; j < 16; j++) vs[j] = 0.0f;
            }
            if (fuse) {
#pragma unroll
                for (int j = 0; j < 16; j++)
                    vs[j] = fmaxf(vs[j] + __ldg(&bias[kb + kq + j]), 0.0f);
            }
#pragma unroll
            for (int j = 0; j < 16; j++) AsT[kq + j][r] = vs[j];
        }

        // ---- W tile load: 32x96 = 3072 elems, 12/thread ----
#pragma unroll
        for (int l = tid; l < GBK * DH; l += 256) {
            int kk = l / DH, n = l - kk * DH;
            Ws[kk][n] = W[(kb + kk) * DH + n];
        }
        __syncthreads();

        // ---- compute ----
#pragma unroll
        for (int k = 0; k < GBK; k++) {
            unsigned long long a[4];
#pragma unroll
            for (int p = 0; p < 4; p++)
                a[p] = *(const unsigned long long*)&AsT[k][ty * 8 + 2 * p];
            unsigned long long w[6];
#pragma unroll
            for (int j = 0; j < 6; j++) w[j] = pack2(Ws[k][tx * 6 + j]);
#pragma unroll
            for (int p = 0; p < 4; p++)
#pragma unroll
                for (int j = 0; j < 6; j++) ffma2(acc[p][j], a[p], w[j]);
        }
        __syncthreads();
    }

    // ---- epilogue: write H and AGG = H * dis^2 ----
#pragma unroll
    for (int p = 0; p < 4; p++) {
        float lo[6], hi[6];
#pragma unroll
        for (int j = 0; j < 6; j++) unpack2(acc[p][j], lo[j], hi[j]);
        int r0 = row0 + ty * 8 + 2 * p;
#pragma unroll
        for (int h = 0; h < 2; h++) {
            int row = r0 + h;
            if (row < NNODES) {
                const float* o = h ? hi : lo;
                float ds = g_dis[row];
                float s = ds * ds;
                float* po = outH + (size_t)row * DH + tx * 6;
                float* pa = agg + (size_t)row * DH + tx * 6;
#pragma unroll
                for (int j = 0; j < 3; j++) {
                    float2 v = make_float2(o[2 * j], o[2 * j + 1]);
                    ((float2*)po)[j] = v;
                    float2 va = make_float2(v.x * s, v.y * s);
                    ((float2*)pa)[j] = va;
                }
            }
        }
    }
}

// ============================ aggregation ============================

// AGG[dst] += H[src] * dis[src]*dis[dst], one thread per (edge, float4 chunk)
__global__ void scatter_kernel(const int* __restrict__ ei) {
    int idx = blockIdx.x * blockDim.x + threadIdx.x;
    int e = idx / C4;
    int c = idx - e * C4;
    if (e >= NEDGES) return;
    int s = __ldg(&ei[e]);
    int d = __ldg(&ei[NEDGES + e]);
    float nrm = __ldg(&g_dis[s]) * __ldg(&g_dis[d]);
    float4 v = __ldg((const float4*)&g_H[s * DH] + c);
    v.x *= nrm; v.y *= nrm; v.z *= nrm; v.w *= nrm;
    float* addr = &g_AGG[d * DH + 4 * c];
    asm volatile("red.global.add.v4.f32 [%0], {%1, %2, %3, %4};"
                 :: "l"(addr), "f"(v.x), "f"(v.y), "f"(v.z), "f"(v.w)
                 : "memory");
}

// out = relu(AGG + b2)
__global__ void final_kernel(const float* __restrict__ b2, float* __restrict__ out) {
    int idx = blockIdx.x * blockDim.x + threadIdx.x;   // float4 index
    int node = idx / C4;
    int c = idx - node * C4;
    if (node >= NNODES) return;
    float4 v = ((const float4*)g_AGG)[idx];
    float4 b = __ldg((const float4*)b2 + c);
    v.x = fmaxf(v.x + b.x, 0.0f);
    v.y = fmaxf(v.y + b.y, 0.0f);
    v.z = fmaxf(v.z + b.z, 0.0f);
    v.w = fmaxf(v.w + b.w, 0.0f);
    ((float4*)out)[idx] = v;
}

// ============================ launch ============================

extern "C" void kernel_launch(void* const* d_in, const int* in_sizes, int n_in,
                              void* d_out, int out_size) {
    const float* x  = (const float*)d_in[0];
    const int*   ei = (const int*)d_in[1];
    const float* W1 = (const float*)d_in[2];
    const float* b1 = (const float*)d_in[3];
    const float* W2 = (const float*)d_in[4];
    const float* b2 = (const float*)d_in[5];
    float* out = (float*)d_out;

    void *pH_v, *pAGG_v;
    cudaGetSymbolAddress(&pH_v, g_H);
    cudaGetSymbolAddress(&pAGG_v, g_AGG);
    float* pH   = (float*)pH_v;
    float* pAGG = (float*)pAGG_v;

    const int T = 256;
    int nBlkN    = (NNODES + T - 1) / T;
    int nBlkE    = (NEDGES + T - 1) / T;
    int nBlkRow4 = (NNODES * C4 + T - 1) / T;     // node x float4-chunk grid
    int nBlkEdg4 = (NEDGES * C4 + T - 1) / T;     // edge x float4-chunk grid
    int nBlkGemm = (NNODES + GBM - 1) / GBM;

    // norm
    deg_init_kernel<<<nBlkN, T>>>();
    deg_count_kernel<<<nBlkE, T>>>(ei);
    deg_rsqrt_kernel<<<nBlkN, T>>>();

    // layer 1: H = x @ W1 ; AGG = H*dis^2 (fused) ; scatter edges
    gemm96_f32x2_kernel<<<nBlkGemm, 256>>>(x, W1, nullptr, pH, pAGG, 0);
    scatter_kernel<<<nBlkEdg4, T>>>(ei);

    // layer 2: H2 = relu(AGG + b1) @ W2 ; AGG = H2*dis^2 (fused) ; scatter
    gemm96_f32x2_kernel<<<nBlkGemm, 256>>>(pAGG, W2, b1, pH, pAGG, 1);
    scatter_kernel<<<nBlkEdg4, T>>>(ei);

    // out = relu(AGG + b2)
    final_kernel<<<nBlkRow4, T>>>(b2, out);
}

// round 4
// speedup vs baseline: 1.7456x; 1.2715x over previous
#include <cuda_runtime.h>

#define NNODES 100000
#define NEDGES 800000
#define DH 96
#define C4 (DH / 4)

// ---- scratch ----
__device__ float g_H[NNODES * DH];
__device__ float g_AGG[NNODES * DH];
__device__ float g_dis[NNODES];
__device__ int   g_cnt[NNODES];      // in-degree (edges only)
__device__ int   g_cur[NNODES];      // fill cursor
__device__ int   g_off[NNODES];      // CSR offsets
__device__ int   g_bsum[256];        // scan block sums
__device__ int   g_csr[NEDGES];      // src ids grouped by dst

// ============================ f32x2 helpers ============================

__device__ __forceinline__ unsigned long long pack2(float x) {
    unsigned long long r;
    asm("mov.b64 %0, {%1, %1};" : "=l"(r) : "f"(x));
    return r;
}
__device__ __forceinline__ void ffma2(unsigned long long& d,
                                      unsigned long long a,
                                      unsigned long long b) {
    asm("fma.rn.f32x2 %0, %1, %2, %0;" : "+l"(d) : "l"(a), "l"(b));
}
__device__ __forceinline__ void unpack2(unsigned long long v, float& lo, float& hi) {
    asm("mov.b64 {%0, %1}, %2;" : "=f"(lo), "=f"(hi) : "l"(v));
}

// ============================ norm + CSR build ============================

__global__ void zero_cnt_kernel() {
    int i = blockIdx.x * blockDim.x + threadIdx.x;
    if (i < NNODES) { g_cnt[i] = 0; g_cur[i] = 0; }
}

__global__ void hist_kernel(const int* __restrict__ ei) {
    int e = blockIdx.x * blockDim.x + threadIdx.x;
    if (e < NEDGES) atomicAdd(&g_cnt[ei[NEDGES + e]], 1);
}

__global__ void dis_kernel() {
    int i = blockIdx.x * blockDim.x + threadIdx.x;
    if (i < NNODES) g_dis[i] = rsqrtf((float)g_cnt[i] + 1.0f);  // +1 self-loop
}

#define SCHUNK 512
#define NSBLK ((NNODES + SCHUNK - 1) / SCHUNK)   // 196

__global__ void scan1_kernel() {
    __shared__ int s[SCHUNK];
    int t = threadIdx.x, b = blockIdx.x;
    int i = b * SCHUNK + t;
    int v = (i < NNODES) ? g_cnt[i] : 0;
    s[t] = v;
    __syncthreads();
#pragma unroll
    for (int off = 1; off < SCHUNK; off <<= 1) {
        int x = (t >= off) ? s[t - off] : 0;
        __syncthreads();
        s[t] += x;
        __syncthreads();
    }
    if (i < NNODES) g_off[i] = s[t] - v;   // exclusive within block
    if (t == SCHUNK - 1) g_bsum[b] = s[t];
}

__global__ void scan2_kernel() {   // single block, 256 threads, NSBLK<=256
    __shared__ int s[256];
    int t = threadIdx.x;
    int v = (t < NSBLK) ? g_bsum[t] : 0;
    s[t] = v;
    __syncthreads();
#pragma unroll
    for (int off = 1; off < 256; off <<= 1) {
        int x = (t >= off) ? s[t - off] : 0;
        __syncthreads();
        s[t] += x;
        __syncthreads();
    }
    if (t < NSBLK) g_bsum[t] = s[t] - v;   // exclusive
}

__global__ void scan3_kernel() {
    int i = blockIdx.x * blockDim.x + threadIdx.x;
    if (i < NNODES) g_off[i] += g_bsum[i / SCHUNK];
}

__global__ void fill_kernel(const int* __restrict__ ei) {
    int e = blockIdx.x * blockDim.x + threadIdx.x;
    if (e >= NEDGES) return;
    int s = ei[e];
    int d = ei[NEDGES + e];
    int pos = g_off[d] + atomicAdd(&g_cur[d], 1);
    g_csr[pos] = s;
}

// ============================ GEMM (f32x2) ============================
// outH[n,96] = A'[n,96] @ W[96,96], A' = fuse ? relu(A+bias) : A
// BM=128, BK=32, 256 thr. Thread tile 8(M, f32x2-paired) x 6(N strided 16).

#define GBM 128
#define GBK 32
#define APITCH 130

__global__ void __launch_bounds__(256, 2)
gemm96_f32x2_kernel(const float* __restrict__ A, const float* __restrict__ W,
                    const float* __restrict__ bias, float* __restrict__ outH,
                    int fuse) {
    __shared__ float AsT[GBK][APITCH];                 // [k][m] transposed
    __shared__ unsigned long long Ws2[GBK][DH];        // [k][n] pre-duplicated

    const int tid = threadIdx.x;
    const int tx = tid & 15;           // n-group: cols tx + 16*j
    const int ty = tid >> 4;           // m-group: rows [ty*8, ty*8+8)
    const int row0 = blockIdx.x * GBM;

    unsigned long long acc[4][6];
#pragma unroll
    for (int p = 0; p < 4; p++)
#pragma unroll
        for (int j = 0; j < 6; j++) acc[p][j] = 0ull;

    const int r  = tid & 127;          // A row within tile (warp = 32 consec rows)
    const int kq = (tid >> 7) << 4;    // 0 or 16

#pragma unroll 1
    for (int kt = 0; kt < 3; kt++) {
        const int kb = kt * GBK;

        // ---- A tile (transposed, conflict-free STS) ----
        {
            int grow = row0 + r;
            float vs[16];
            if (grow < NNODES) {
                const float4* ap = (const float4*)(A + (size_t)grow * DH + kb + kq);
                float4 v0 = ap[0], v1 = ap[1], v2 = ap[2], v3 = ap[3];
                vs[0]=v0.x; vs[1]=v0.y; vs[2]=v0.z; vs[3]=v0.w;
                vs[4]=v1.x; vs[5]=v1.y; vs[6]=v1.z; vs[7]=v1.w;
                vs[8]=v2.x; vs[9]=v2.y; vs[10]=v2.z; vs[11]=v2.w;
                vs[12]=v3.x; vs[13]=v3.y; vs[14]=v3.z; vs[15]=v3.w;
            } else {
#pragma unroll
                for (int j = 0; j < 16; j++) vs[j] = 0.0f;
            }
            if (fuse) {
#pragma unroll
                for (int j = 0; j < 16; j++)
                    vs[j] = fmaxf(vs[j] + __ldg(&bias[kb + kq + j]), 0.0f);
            }
#pragma unroll
            for (int j = 0; j < 16; j++) AsT[kq + j][r] = vs[j];
        }

        // ---- W tile, pre-duplicated to f32x2 ----
#pragma unroll
        for (int l = tid; l < GBK * DH; l += 256) {
            int kk = l / DH, n = l - kk * DH;
            Ws2[kk][n] = pack2(W[(kb + kk) * DH + n]);
        }
        __syncthreads();

        // ---- compute: 4 LDS.64(A) + 6 LDS.64(W) + 24 FFMA2 per k ----
#pragma unroll
        for (int k = 0; k < GBK; k++) {
            unsigned long long a[4];
#pragma unroll
            for (int p = 0; p < 4; p++)
                a[p] = *(const unsigned long long*)&AsT[k][ty * 8 + 2 * p];
            unsigned long long w[6];
#pragma unroll
            for (int j = 0; j < 6; j++) w[j] = Ws2[k][tx + 16 * j];
#pragma unroll
            for (int p = 0; p < 4; p++)
#pragma unroll
                for (int j = 0; j < 6; j++) ffma2(acc[p][j], a[p], w[j]);
        }
        __syncthreads();
    }

    // ---- epilogue ----
#pragma unroll
    for (int p = 0; p < 4; p++) {
        float lo[6], hi[6];
#pragma unroll
        for (int j = 0; j < 6; j++) unpack2(acc[p][j], lo[j], hi[j]);
        int r0 = row0 + ty * 8 + 2 * p;
#pragma unroll
        for (int h = 0; h < 2; h++) {
            int row = r0 + h;
            if (row < NNODES) {
                const float* o = h ? hi : lo;
                float* po = outH + (size_t)row * DH + tx;
#pragma unroll
                for (int j = 0; j < 6; j++) po[16 * j] = o[j];
            }
        }
    }
}

// ============================ gather aggregation ============================
// One warp per node. agg[d] = dis[d] * (dis[d]*H[d] + sum_{s in N(d)} dis[s]*H[s])
// mode 0: write to g_AGG raw. mode 1: write relu(agg + bias) to out.

__global__ void __launch_bounds__(256)
gather_kernel(const float* __restrict__ bias, float* __restrict__ out, int mode) {
    int gwid = (blockIdx.x * blockDim.x + threadIdx.x) >> 5;
    int lid = threadIdx.x & 31;
    if (gwid >= NNODES) return;

    const bool active = lid < C4;
    float dd = g_dis[gwid];
    float4 acc = make_float4(0.f, 0.f, 0.f, 0.f);
    if (active) {
        float4 h = __ldg((const float4*)&g_H[(size_t)gwid * DH] + lid);
        acc.x = h.x * dd; acc.y = h.y * dd; acc.z = h.z * dd; acc.w = h.w * dd;
    }

    int start = g_off[gwid];
    int deg   = g_cnt[gwid];
#pragma unroll 4
    for (int i = 0; i < deg; i++) {
        int s = __ldg(&g_csr[start + i]);
        float ds = __ldg(&g_dis[s]);
        if (active) {
            float4 h = __ldg((const float4*)&g_H[(size_t)s * DH] + lid);
            acc.x = fmaf(ds, h.x, acc.x);
            acc.y = fmaf(ds, h.y, acc.y);
            acc.z = fmaf(ds, h.z, acc.z);
            acc.w = fmaf(ds, h.w, acc.w);
        }
    }

    if (active) {
        acc.x *= dd; acc.y *= dd; acc.z *= dd; acc.w *= dd;
        if (mode == 1) {
            float4 b = __ldg((const float4*)bias + lid);
            acc.x = fmaxf(acc.x + b.x, 0.0f);
            acc.y = fmaxf(acc.y + b.y, 0.0f);
            acc.z = fmaxf(acc.z + b.z, 0.0f);
            acc.w = fmaxf(acc.w + b.w, 0.0f);
        }
        ((float4*)(out + (size_t)gwid * DH))[lid] = acc;
    }
}

// ============================ launch ============================

extern "C" void kernel_launch(void* const* d_in, const int* in_sizes, int n_in,
                              void* d_out, int out_size) {
    const float* x  = (const float*)d_in[0];
    const int*   ei = (const int*)d_in[1];
    const float* W1 = (const float*)d_in[2];
    const float* b1 = (const float*)d_in[3];
    const float* W2 = (const float*)d_in[4];
    const float* b2 = (const float*)d_in[5];
    float* out = (float*)d_out;

    void *pH_v, *pAGG_v;
    cudaGetSymbolAddress(&pH_v, g_H);
    cudaGetSymbolAddress(&pAGG_v, g_AGG);
    float* pH   = (float*)pH_v;
    float* pAGG = (float*)pAGG_v;

    const int T = 256;
    int nBlkN    = (NNODES + T - 1) / T;
    int nBlkE    = (NEDGES + T - 1) / T;
    int nBlkGemm = (NNODES + GBM - 1) / GBM;
    int nBlkGath = (NNODES * 32 + T - 1) / T;    // one warp per node

    // norm + CSR
    zero_cnt_kernel<<<nBlkN, T>>>();
    hist_kernel<<<nBlkE, T>>>(ei);
    dis_kernel<<<nBlkN, T>>>();
    scan1_kernel<<<NSBLK, SCHUNK>>>();
    scan2_kernel<<<1, 256>>>();
    scan3_kernel<<<nBlkN, T>>>();
    fill_kernel<<<nBlkE, T>>>(ei);

    // layer 1
    gemm96_f32x2_kernel<<<nBlkGemm, 256>>>(x, W1, nullptr, pH, 0);
    gather_kernel<<<nBlkGath, T>>>(nullptr, pAGG, 0);

    // layer 2
    gemm96_f32x2_kernel<<<nBlkGemm, 256>>>(pAGG, W2, b1, pH, 1);
    gather_kernel<<<nBlkGath, T>>>(b2, out, 1);
}

// round 6
// speedup vs baseline: 2.2748x; 1.3032x over previous
#include <cuda_runtime.h>
#include <cuda_bf16.h>
#include <cstdint>

#define NNODES 100000
#define NEDGES 800000
#define DH 96
#define C4 (DH / 4)

// ---- scratch ----
__device__ float g_H[NNODES * DH];      // GEMM output, row-major [node][96]
__device__ float g_AGG[NNODES * DH];    // aggregation output
__device__ float g_dis[NNODES];
__device__ int   g_cnt[NNODES];
__device__ int   g_cur[NNODES];
__device__ int   g_off[NNODES];
__device__ int   g_bsum[256];
__device__ int   g_csr[NEDGES];
// B fragments: [layer][var(hi/lo)][np(2)][kt(6)][nt(6)][lane(32)] -> uint2
__device__ uint2 g_Bfrag[2 * 2 * 2 * 6 * 6 * 32];

// ============================ helpers ============================

// pack two floats to bf16x2: low half = first arg
__device__ __forceinline__ uint32_t cvt_bf16x2(float lo, float hi) {
    uint32_t r;
    asm("cvt.rn.satfinite.bf16x2.f32 %0, %1, %2;" : "=r"(r) : "f"(hi), "f"(lo));
    return r;
}

__device__ __forceinline__ void mma_bf16(float* c, const uint32_t* a,
                                         uint32_t b0, uint32_t b1) {
    asm volatile(
        "mma.sync.aligned.m16n8k16.row.col.f32.bf16.bf16.f32 "
        "{%0,%1,%2,%3}, {%4,%5,%6,%7}, {%8,%9}, {%0,%1,%2,%3};"
        : "+f"(c[0]), "+f"(c[1]), "+f"(c[2]), "+f"(c[3])
        : "r"(a[0]), "r"(a[1]), "r"(a[2]), "r"(a[3]), "r"(b0), "r"(b1));
}

// ============================ norm + CSR build ============================

__global__ void zero_cnt_kernel() {
    int i = blockIdx.x * blockDim.x + threadIdx.x;
    if (i < NNODES) { g_cnt[i] = 0; g_cur[i] = 0; }
}
__global__ void hist_kernel(const int* __restrict__ ei) {
    int e = blockIdx.x * blockDim.x + threadIdx.x;
    if (e < NEDGES) atomicAdd(&g_cnt[ei[NEDGES + e]], 1);
}
__global__ void dis_kernel() {
    int i = blockIdx.x * blockDim.x + threadIdx.x;
    if (i < NNODES) g_dis[i] = rsqrtf((float)g_cnt[i] + 1.0f);
}

#define SCHUNK 512
#define NSBLK ((NNODES + SCHUNK - 1) / SCHUNK)

__global__ void scan1_kernel() {
    __shared__ int s[SCHUNK];
    int t = threadIdx.x, b = blockIdx.x;
    int i = b * SCHUNK + t;
    int v = (i < NNODES) ? g_cnt[i] : 0;
    s[t] = v;
    __syncthreads();
#pragma unroll
    for (int off = 1; off < SCHUNK; off <<= 1) {
        int x = (t >= off) ? s[t - off] : 0;
        __syncthreads();
        s[t] += x;
        __syncthreads();
    }
    if (i < NNODES) g_off[i] = s[t] - v;
    if (t == SCHUNK - 1) g_bsum[b] = s[t];
}
__global__ void scan2_kernel() {
    __shared__ int s[256];
    int t = threadIdx.x;
    int v = (t < NSBLK) ? g_bsum[t] : 0;
    s[t] = v;
    __syncthreads();
#pragma unroll
    for (int off = 1; off < 256; off <<= 1) {
        int x = (t >= off) ? s[t - off] : 0;
        __syncthreads();
        s[t] += x;
        __syncthreads();
    }
    if (t < NSBLK) g_bsum[t] = s[t] - v;
}
__global__ void scan3_kernel() {
    int i = blockIdx.x * blockDim.x + threadIdx.x;
    if (i < NNODES) g_off[i] += g_bsum[i / SCHUNK];
}
__global__ void fill_kernel(const int* __restrict__ ei) {
    int e = blockIdx.x * blockDim.x + threadIdx.x;
    if (e >= NEDGES) return;
    int s = ei[e];
    int d = ei[NEDGES + e];
    int pos = g_off[d] + atomicAdd(&g_cur[d], 1);
    g_csr[pos] = s;
}

// ============================ W fragment prep ============================
// For mma.sync m16n8k16 row.col, B fragment (16x8, col n = lane/4):
//   b0=(k0,n) b1=(k0+1,n) b2=(k0+8,n) b3=(k0+9,n), k0 = kt*16 + (lane%4)*2
// reg0 = pack(b0,b1), reg1 = pack(b2,b3).  var: 0=hi split, 1=lo split.

__global__ void wprep_kernel(const float* __restrict__ W1, const float* __restrict__ W2) {
    int idx = blockIdx.x * blockDim.x + threadIdx.x;
    if (idx >= 2 * 2 * 2 * 6 * 6 * 32) return;
    int lane = idx & 31;
    int t = idx >> 5;
    int nt = t % 6;  t /= 6;
    int kt = t % 6;  t /= 6;
    int np = t % 2;  t /= 2;
    int var = t % 2; t /= 2;
    int layer = t;
    const float* W = layer ? W2 : W1;

    int n  = np * 48 + nt * 8 + (lane >> 2);
    int k0 = kt * 16 + (lane & 3) * 2;
    float v[4];
#pragma unroll
    for (int i = 0; i < 4; i++) {
        int k = k0 + (i & 1) + (i >> 1) * 8;
        float w = W[k * DH + n];
        float hi = __bfloat162float(__float2bfloat16(w));
        v[i] = var ? (w - hi) : hi;
    }
    g_Bfrag[idx] = make_uint2(cvt_bf16x2(v[0], v[1]), cvt_bf16x2(v[2], v[3]));
}

// ============================ HMMA GEMM ============================
// H[n,96] = A'[n,96] @ W[96,96], A' = fuse ? relu(A+bias) : A
// bf16 3-product split. 256 thr = 8 warps (4M x 2N). CTA: M=128, N=96, K=96.

#define GBM 128
#define APITCH 104                    // bf16 elems per row (208 B)
#define AROW_BYTES (APITCH * 2)
#define SM_AHI 0
#define SM_ALO (GBM * AROW_BYTES)     // 26624
#define GEMM_SMEM (2 * GBM * AROW_BYTES)

__global__ void __launch_bounds__(256)
gemm_hmma_kernel(const float* __restrict__ A, const uint2* __restrict__ Bfrag,
                 const float* __restrict__ bias, float* __restrict__ H, int fuse) {
    extern __shared__ char smem[];
    const int tid = threadIdx.x;
    const int lane = tid & 31;
    const int wid = tid >> 5;
    const int wm = wid & 3;            // M partition (32 rows)
    const int wn = wid >> 2;           // N partition (48 cols)
    const int row0 = blockIdx.x * GBM;

    // ---- stage A: load fp32, fuse, split to bf16 hi/lo in smem ----
    {
        const int r = tid >> 1;                 // 0..127
        const int cb = (tid & 1) * 48;          // col base
        const int grow = row0 + r;
        char* phi = smem + SM_AHI + r * AROW_BYTES;
        char* plo = smem + SM_ALO + r * AROW_BYTES;
#pragma unroll
        for (int q = 0; q < 12; q++) {
            const int k0 = cb + q * 4;
            float4 v;
            if (grow < NNODES) {
                v = *(const float4*)(A + (size_t)grow * DH + k0);
                if (fuse) {
                    const float4 b = *(const float4*)(bias + k0);
                    v.x = fmaxf(v.x + b.x, 0.0f);
                    v.y = fmaxf(v.y + b.y, 0.0f);
                    v.z = fmaxf(v.z + b.z, 0.0f);
                    v.w = fmaxf(v.w + b.w, 0.0f);
                }
            } else {
                v = make_float4(0.f, 0.f, 0.f, 0.f);
            }
            uint32_t h01 = cvt_bf16x2(v.x, v.y);
            uint32_t h23 = cvt_bf16x2(v.z, v.w);
            float lx = v.x - __uint_as_float(h01 << 16);
            float ly = v.y - __uint_as_float(h01 & 0xFFFF0000u);
            float lz = v.z - __uint_as_float(h23 << 16);
            float lw = v.w - __uint_as_float(h23 & 0xFFFF0000u);
            *(uint2*)(phi + k0 * 2) = make_uint2(h01, h23);
            *(uint2*)(plo + k0 * 2) = make_uint2(cvt_bf16x2(lx, ly), cvt_bf16x2(lz, lw));
        }
    }
    __syncthreads();

    // ---- mma mainloop ----
    float acc[2][6][4];
#pragma unroll
    for (int m = 0; m < 2; m++)
#pragma unroll
        for (int nt = 0; nt < 6; nt++)
#pragma unroll
            for (int i = 0; i < 4; i++) acc[m][nt][i] = 0.0f;

    const int fr = (lane >> 2);        // fragment row within 8
    const int fk = (lane & 3) * 2;     // fragment k pair

#pragma unroll
    for (int kt = 0; kt < 6; kt++) {
        uint32_t ahi[2][4], alo[2][4];
#pragma unroll
        for (int m = 0; m < 2; m++) {
            const int r = wm * 32 + m * 16 + fr;
            const int kb = (kt * 16 + fk) * 2;          // byte offset of k pair
            const char* ph = smem + SM_AHI + r * AROW_BYTES + kb;
            const char* pl = smem + SM_ALO + r * AROW_BYTES + kb;
            ahi[m][0] = *(const uint32_t*)ph;
            ahi[m][1] = *(const uint32_t*)(ph + 8 * AROW_BYTES);
            ahi[m][2] = *(const uint32_t*)(ph + 16);
            ahi[m][3] = *(const uint32_t*)(ph + 8 * AROW_BYTES + 16);
            alo[m][0] = *(const uint32_t*)pl;
            alo[m][1] = *(const uint32_t*)(pl + 8 * AROW_BYTES);
            alo[m][2] = *(const uint32_t*)(pl + 16);
            alo[m][3] = *(const uint32_t*)(pl + 8 * AROW_BYTES + 16);
        }
#pragma unroll
        for (int nt = 0; nt < 6; nt++) {
            // index: ((var*2 + np)*6 + kt)*6 + nt, per-lane uint2
            const uint2 bhi = Bfrag[(((0 * 2 + wn) * 6 + kt) * 6 + nt) * 32 + lane];
            const uint2 blo = Bfrag[(((1 * 2 + wn) * 6 + kt) * 6 + nt) * 32 + lane];
#pragma unroll
            for (int m = 0; m < 2; m++) {
                mma_bf16(acc[m][nt], ahi[m], bhi.x, bhi.y);
                mma_bf16(acc[m][nt], ahi[m], blo.x, blo.y);
                mma_bf16(acc[m][nt], alo[m], bhi.x, bhi.y);
            }
        }
    }

    // ---- epilogue: row-major H ----
#pragma unroll
    for (int m = 0; m < 2; m++) {
        const int r = row0 + wm * 32 + m * 16 + fr;
#pragma unroll
        for (int nt = 0; nt < 6; nt++) {
            const int col = wn * 48 + nt * 8 + fk;
            if (r < NNODES)
                *(float2*)(H + (size_t)r * DH + col) = make_float2(acc[m][nt][0], acc[m][nt][1]);
            if (r + 8 < NNODES)
                *(float2*)(H + (size_t)(r + 8) * DH + col) = make_float2(acc[m][nt][2], acc[m][nt][3]);
        }
    }
}

// ============================ gather aggregation ============================
// One warp per node (row-major H). agg[d] = dis[d]*(dis[d]*H[d] + sum dis[s]*H[s])

__global__ void __launch_bounds__(256)
gather_kernel(const float* __restrict__ bias, float* __restrict__ out, int mode) {
    int gwid = (blockIdx.x * blockDim.x + threadIdx.x) >> 5;
    int lid = threadIdx.x & 31;
    if (gwid >= NNODES) return;

    const bool active = lid < C4;
    float dd = g_dis[gwid];
    float4 acc = make_float4(0.f, 0.f, 0.f, 0.f);
    if (active) {
        float4 h = __ldg((const float4*)&g_H[(size_t)gwid * DH] + lid);
        acc.x = h.x * dd; acc.y = h.y * dd; acc.z = h.z * dd; acc.w = h.w * dd;
    }

    int start = g_off[gwid];
    int deg   = g_cnt[gwid];
#pragma unroll 4
    for (int i = 0; i < deg; i++) {
        int s = __ldg(&g_csr[start + i]);
        float ds = __ldg(&g_dis[s]);
        if (active) {
            float4 h = __ldg((const float4*)&g_H[(size_t)s * DH] + lid);
            acc.x = fmaf(ds, h.x, acc.x);
            acc.y = fmaf(ds, h.y, acc.y);
            acc.z = fmaf(ds, h.z, acc.z);
            acc.w = fmaf(ds, h.w, acc.w);
        }
    }

    if (active) {
        acc.x *= dd; acc.y *= dd; acc.z *= dd; acc.w *= dd;
        if (mode == 1) {
            float4 b = __ldg((const float4*)bias + lid);
            acc.x = fmaxf(acc.x + b.x, 0.0f);
            acc.y = fmaxf(acc.y + b.y, 0.0f);
            acc.z = fmaxf(acc.z + b.z, 0.0f);
            acc.w = fmaxf(acc.w + b.w, 0.0f);
        }
        ((float4*)(out + (size_t)gwid * DH))[lid] = acc;
    }
}

// ============================ launch ============================

extern "C" void kernel_launch(void* const* d_in, const int* in_sizes, int n_in,
                              void* d_out, int out_size) {
    const float* x  = (const float*)d_in[0];
    const int*   ei = (const int*)d_in[1];
    const float* W1 = (const float*)d_in[2];
    const float* b1 = (const float*)d_in[3];
    const float* W2 = (const float*)d_in[4];
    const float* b2 = (const float*)d_in[5];
    float* out = (float*)d_out;

    void *pH_v, *pAGG_v, *pBf_v;
    cudaGetSymbolAddress(&pH_v, g_H);
    cudaGetSymbolAddress(&pAGG_v, g_AGG);
    cudaGetSymbolAddress(&pBf_v, g_Bfrag);
    float* pH   = (float*)pH_v;
    float* pAGG = (float*)pAGG_v;
    const uint2* pBf = (const uint2*)pBf_v;

    cudaFuncSetAttribute(gemm_hmma_kernel,
                         cudaFuncAttributeMaxDynamicSharedMemorySize, GEMM_SMEM);

    const int T = 256;
    int nBlkN    = (NNODES + T - 1) / T;
    int nBlkE    = (NEDGES + T - 1) / T;
    int nBlkGemm = (NNODES + GBM - 1) / GBM;
    int nBlkGath = (NNODES * 32 + T - 1) / T;
    int nFrag    = 2 * 2 * 2 * 6 * 6 * 32;
    int nBlkWp   = (nFrag + T - 1) / T;

    // norm + CSR + W prep
    zero_cnt_kernel<<<nBlkN, T>>>();
    hist_kernel<<<nBlkE, T>>>(ei);
    dis_kernel<<<nBlkN, T>>>();
    scan1_kernel<<<NSBLK, SCHUNK>>>();
    scan2_kernel<<<1, 256>>>();
    scan3_kernel<<<nBlkN, T>>>();
    fill_kernel<<<nBlkE, T>>>(ei);
    wprep_kernel<<<nBlkWp, T>>>(W1, W2);

    // layer 1
    gemm_hmma_kernel<<<nBlkGemm, 256, GEMM_SMEM>>>(x, pBf, nullptr, pH, 0);
    gather_kernel<<<nBlkGath, T>>>(nullptr, pAGG, 0);

    // layer 2 (Bfrag offset: layer stride = 2*2*6*6*32 = 4608)
    gemm_hmma_kernel<<<nBlkGemm, 256, GEMM_SMEM>>>(pAGG, pBf + 4608, b1, pH, 1);
    gather_kernel<<<nBlkGath, T>>>(b2, out, 1);
}

// round 7
// speedup vs baseline: 2.4371x; 1.0713x over previous
#include <cuda_runtime.h>
#include <cuda_bf16.h>
#include <cstdint>

#define NNODES 100000
#define NEDGES 800000
#define DH 96
#define C4 (DH / 4)

// ---- scratch ----
__device__ float g_H[NNODES * DH];      // GEMM output pre-scaled: Hs[r] = dis[r]*H[r]
__device__ float g_AGG[NNODES * DH];
__device__ float g_dis[NNODES];
__device__ int   g_cnt[NNODES];
__device__ int   g_cur[NNODES];
__device__ int   g_off[NNODES];         // per-chunk exclusive prefix (bsum NOT applied)
__device__ int   g_bsum[256];           // exclusive chunk sums
__device__ int   g_csr[NEDGES];
// B fragments: [layer][var(hi/lo)][np(2)][kt(6)][nt(6)][lane(32)] -> uint2
__device__ uint2 g_Bfrag[2 * 2 * 2 * 6 * 6 * 32];

// ============================ helpers ============================

__device__ __forceinline__ uint32_t cvt_bf16x2(float lo, float hi) {
    uint32_t r;
    asm("cvt.rn.satfinite.bf16x2.f32 %0, %1, %2;" : "=r"(r) : "f"(hi), "f"(lo));
    return r;
}

__device__ __forceinline__ void mma_bf16(float* c, const uint32_t* a,
                                         uint32_t b0, uint32_t b1) {
    asm volatile(
        "mma.sync.aligned.m16n8k16.row.col.f32.bf16.bf16.f32 "
        "{%0,%1,%2,%3}, {%4,%5,%6,%7}, {%8,%9}, {%0,%1,%2,%3};"
        : "+f"(c[0]), "+f"(c[1]), "+f"(c[2]), "+f"(c[3])
        : "r"(a[0]), "r"(a[1]), "r"(a[2]), "r"(a[3]), "r"(b0), "r"(b1));
}

// ============================ norm + CSR build ============================

__global__ void zero_cnt_kernel() {
    int i = blockIdx.x * blockDim.x + threadIdx.x;
    if (i < NNODES) { g_cnt[i] = 0; g_cur[i] = 0; }
}
__global__ void hist_kernel(const int* __restrict__ ei) {
    int e = blockIdx.x * blockDim.x + threadIdx.x;
    if (e < NEDGES) atomicAdd(&g_cnt[ei[NEDGES + e]], 1);
}

#define SCHUNK 512
#define NSBLK ((NNODES + SCHUNK - 1) / SCHUNK)   // 196

// shuffle-based per-chunk exclusive scan of g_cnt; also computes g_dis.
__global__ void scan1_kernel() {
    __shared__ int wsum[16];
    const int t = threadIdx.x;
    const int lane = t & 31, warp = t >> 5;
    const int i = blockIdx.x * SCHUNK + t;
    const int v = (i < NNODES) ? g_cnt[i] : 0;
    int x = v;
#pragma unroll
    for (int o = 1; o < 32; o <<= 1) {
        int y = __shfl_up_sync(0xFFFFFFFF, x, o);
        if (lane >= o) x += y;
    }
    if (lane == 31) wsum[warp] = x;
    __syncthreads();
    if (warp == 0) {
        int s = (lane < 16) ? wsum[lane] : 0;
#pragma unroll
        for (int o = 1; o < 16; o <<= 1) {
            int y = __shfl_up_sync(0xFFFFFFFF, s, o);
            if (lane >= o) s += y;
        }
        if (lane < 16) wsum[lane] = s;    // inclusive warp totals
    }
    __syncthreads();
    const int base = (warp > 0) ? wsum[warp - 1] : 0;
    if (i < NNODES) {
        g_off[i] = base + x - v;          // exclusive within chunk
        g_dis[i] = rsqrtf((float)v + 1.0f);
    }
    if (t == SCHUNK - 1) g_bsum[blockIdx.x] = base + x;   // chunk total
}

__global__ void scan2_kernel() {   // exclusive scan of 196 chunk totals
    __shared__ int s[256];
    int t = threadIdx.x;
    int v = (t < NSBLK) ? g_bsum[t] : 0;
    s[t] = v;
    __syncthreads();
#pragma unroll
    for (int off = 1; off < 256; off <<= 1) {
        int x = (t >= off) ? s[t - off] : 0;
        __syncthreads();
        s[t] += x;
        __syncthreads();
    }
    if (t < NSBLK) g_bsum[t] = s[t] - v;
}

__global__ void fill_kernel(const int* __restrict__ ei) {
    int e = blockIdx.x * blockDim.x + threadIdx.x;
    if (e >= NEDGES) return;
    int s = ei[e];
    int d = ei[NEDGES + e];
    int pos = g_off[d] + g_bsum[d >> 9] + atomicAdd(&g_cur[d], 1);
    g_csr[pos] = s;
}

// ============================ W fragment prep ============================

__global__ void wprep_kernel(const float* __restrict__ W1, const float* __restrict__ W2) {
    int idx = blockIdx.x * blockDim.x + threadIdx.x;
    if (idx >= 2 * 2 * 2 * 6 * 6 * 32) return;
    int lane = idx & 31;
    int t = idx >> 5;
    int nt = t % 6;  t /= 6;
    int kt = t % 6;  t /= 6;
    int np = t % 2;  t /= 2;
    int var = t % 2; t /= 2;
    int layer = t;
    const float* W = layer ? W2 : W1;

    int n  = np * 48 + nt * 8 + (lane >> 2);
    int k0 = kt * 16 + (lane & 3) * 2;
    float v[4];
#pragma unroll
    for (int i = 0; i < 4; i++) {
        int k = k0 + (i & 1) + (i >> 1) * 8;
        float w = W[k * DH + n];
        float hi = __bfloat162float(__float2bfloat16(w));
        v[i] = var ? (w - hi) : hi;
    }
    g_Bfrag[idx] = make_uint2(cvt_bf16x2(v[0], v[1]), cvt_bf16x2(v[2], v[3]));
}

// ============================ HMMA GEMM ============================
// Hs[n,96] = dis[n] * (A'[n,96] @ W[96,96]), A' = fuse ? relu(A+bias) : A
// bf16 3-product split. 256 thr = 8 warps (4M x 2N). CTA: M=128, N=96, K=96.

#define GBM 128
#define APITCH 104
#define AROW_BYTES (APITCH * 2)
#define SM_AHI 0
#define SM_ALO (GBM * AROW_BYTES)
#define GEMM_SMEM (2 * GBM * AROW_BYTES)

__global__ void __launch_bounds__(256)
gemm_hmma_kernel(const float* __restrict__ A, const uint2* __restrict__ Bfrag,
                 const float* __restrict__ bias, float* __restrict__ H, int fuse) {
    extern __shared__ char smem[];
    const int tid = threadIdx.x;
    const int lane = tid & 31;
    const int wid = tid >> 5;
    const int wm = wid & 3;
    const int wn = wid >> 2;
    const int row0 = blockIdx.x * GBM;

    // ---- stage A: load fp32, fuse, split to bf16 hi/lo in smem ----
    {
        const int r = tid >> 1;
        const int cb = (tid & 1) * 48;
        const int grow = row0 + r;
        char* phi = smem + SM_AHI + r * AROW_BYTES;
        char* plo = smem + SM_ALO + r * AROW_BYTES;
#pragma unroll
        for (int q = 0; q < 12; q++) {
            const int k0 = cb + q * 4;
            float4 v;
            if (grow < NNODES) {
                v = *(const float4*)(A + (size_t)grow * DH + k0);
                if (fuse) {
                    const float4 b = *(const float4*)(bias + k0);
                    v.x = fmaxf(v.x + b.x, 0.0f);
                    v.y = fmaxf(v.y + b.y, 0.0f);
                    v.z = fmaxf(v.z + b.z, 0.0f);
                    v.w = fmaxf(v.w + b.w, 0.0f);
                }
            } else {
                v = make_float4(0.f, 0.f, 0.f, 0.f);
            }
            uint32_t h01 = cvt_bf16x2(v.x, v.y);
            uint32_t h23 = cvt_bf16x2(v.z, v.w);
            float lx = v.x - __uint_as_float(h01 << 16);
            float ly = v.y - __uint_as_float(h01 & 0xFFFF0000u);
            float lz = v.z - __uint_as_float(h23 << 16);
            float lw = v.w - __uint_as_float(h23 & 0xFFFF0000u);
            *(uint2*)(phi + k0 * 2) = make_uint2(h01, h23);
            *(uint2*)(plo + k0 * 2) = make_uint2(cvt_bf16x2(lx, ly), cvt_bf16x2(lz, lw));
        }
    }
    __syncthreads();

    // ---- mma mainloop ----
    float acc[2][6][4];
#pragma unroll
    for (int m = 0; m < 2; m++)
#pragma unroll
        for (int nt = 0; nt < 6; nt++)
#pragma unroll
            for (int i = 0; i < 4; i++) acc[m][nt][i] = 0.0f;

    const int fr = (lane >> 2);
    const int fk = (lane & 3) * 2;

#pragma unroll
    for (int kt = 0; kt < 6; kt++) {
        uint32_t ahi[2][4], alo[2][4];
#pragma unroll
        for (int m = 0; m < 2; m++) {
            const int r = wm * 32 + m * 16 + fr;
            const int kb = (kt * 16 + fk) * 2;
            const char* ph = smem + SM_AHI + r * AROW_BYTES + kb;
            const char* pl = smem + SM_ALO + r * AROW_BYTES + kb;
            ahi[m][0] = *(const uint32_t*)ph;
            ahi[m][1] = *(const uint32_t*)(ph + 8 * AROW_BYTES);
            ahi[m][2] = *(const uint32_t*)(ph + 16);
            ahi[m][3] = *(const uint32_t*)(ph + 8 * AROW_BYTES + 16);
            alo[m][0] = *(const uint32_t*)pl;
            alo[m][1] = *(const uint32_t*)(pl + 8 * AROW_BYTES);
            alo[m][2] = *(const uint32_t*)(pl + 16);
            alo[m][3] = *(const uint32_t*)(pl + 8 * AROW_BYTES + 16);
        }
#pragma unroll
        for (int nt = 0; nt < 6; nt++) {
            const uint2 bhi = Bfrag[(((0 * 2 + wn) * 6 + kt) * 6 + nt) * 32 + lane];
            const uint2 blo = Bfrag[(((1 * 2 + wn) * 6 + kt) * 6 + nt) * 32 + lane];
#pragma unroll
            for (int m = 0; m < 2; m++) {
                mma_bf16(acc[m][nt], ahi[m], bhi.x, bhi.y);
                mma_bf16(acc[m][nt], ahi[m], blo.x, blo.y);
                mma_bf16(acc[m][nt], alo[m], bhi.x, bhi.y);
            }
        }
    }

    // ---- epilogue: Hs = dis[r] * H[r], row-major ----
#pragma unroll
    for (int m = 0; m < 2; m++) {
        const int r = row0 + wm * 32 + m * 16 + fr;
        const float d0 = (r < NNODES) ? g_dis[r] : 0.0f;
        const float d1 = (r + 8 < NNODES) ? g_dis[r + 8] : 0.0f;
#pragma unroll
        for (int nt = 0; nt < 6; nt++) {
            const int col = wn * 48 + nt * 8 + fk;
            if (r < NNODES)
                *(float2*)(H + (size_t)r * DH + col) =
                    make_float2(acc[m][nt][0] * d0, acc[m][nt][1] * d0);
            if (r + 8 < NNODES)
                *(float2*)(H + (size_t)(r + 8) * DH + col) =
                    make_float2(acc[m][nt][2] * d1, acc[m][nt][3] * d1);
        }
    }
}

// ============================ gather aggregation ============================
// One warp per node. agg[d] = dis[d] * (Hs[d] + sum_{s in N(d)} Hs[s])
// (Hs already carries the source-side dis factor.)

__global__ void __launch_bounds__(256)
gather_kernel(const float* __restrict__ bias, float* __restrict__ out, int mode) {
    int gwid = (blockIdx.x * blockDim.x + threadIdx.x) >> 5;
    int lid = threadIdx.x & 31;
    if (gwid >= NNODES) return;

    const bool active = lid < C4;
    float4 acc = make_float4(0.f, 0.f, 0.f, 0.f);
    if (active)
        acc = __ldg((const float4*)&g_H[(size_t)gwid * DH] + lid);   // self term

    int start = g_off[gwid] + g_bsum[gwid >> 9];
    int deg   = g_cnt[gwid];
#pragma unroll 4
    for (int i = 0; i < deg; i++) {
        int s = __ldg(&g_csr[start + i]);
        if (active) {
            float4 h = __ldg((const float4*)&g_H[(size_t)s * DH] + lid);
            acc.x += h.x; acc.y += h.y; acc.z += h.z; acc.w += h.w;
        }
    }

    if (active) {
        float dd = g_dis[gwid];
        acc.x *= dd; acc.y *= dd; acc.z *= dd; acc.w *= dd;
        if (mode == 1) {
            float4 b = __ldg((const float4*)bias + lid);
            acc.x = fmaxf(acc.x + b.x, 0.0f);
            acc.y = fmaxf(acc.y + b.y, 0.0f);
            acc.z = fmaxf(acc.z + b.z, 0.0f);
            acc.w = fmaxf(acc.w + b.w, 0.0f);
        }
        ((float4*)(out + (size_t)gwid * DH))[lid] = acc;
    }
}

// ============================ launch ============================

extern "C" void kernel_launch(void* const* d_in, const int* in_sizes, int n_in,
                              void* d_out, int out_size) {
    const float* x  = (const float*)d_in[0];
    const int*   ei = (const int*)d_in[1];
    const float* W1 = (const float*)d_in[2];
    const float* b1 = (const float*)d_in[3];
    const float* W2 = (const float*)d_in[4];
    const float* b2 = (const float*)d_in[5];
    float* out = (float*)d_out;

    void *pH_v, *pAGG_v, *pBf_v;
    cudaGetSymbolAddress(&pH_v, g_H);
    cudaGetSymbolAddress(&pAGG_v, g_AGG);
    cudaGetSymbolAddress(&pBf_v, g_Bfrag);
    float* pH   = (float*)pH_v;
    float* pAGG = (float*)pAGG_v;
    const uint2* pBf = (const uint2*)pBf_v;

    cudaFuncSetAttribute(gemm_hmma_kernel,
                         cudaFuncAttributeMaxDynamicSharedMemorySize, GEMM_SMEM);

    const int T = 256;
    int nBlkN    = (NNODES + T - 1) / T;
    int nBlkE    = (NEDGES + T - 1) / T;
    int nBlkGemm = (NNODES + GBM - 1) / GBM;
    int nBlkGath = (NNODES * 32 + T - 1) / T;
    int nFrag    = 2 * 2 * 2 * 6 * 6 * 32;
    int nBlkWp   = (nFrag + T - 1) / T;

    // norm + CSR + W prep
    zero_cnt_kernel<<<nBlkN, T>>>();
    hist_kernel<<<nBlkE, T>>>(ei);
    scan1_kernel<<<NSBLK, SCHUNK>>>();    // also computes g_dis
    scan2_kernel<<<1, 256>>>();
    fill_kernel<<<nBlkE, T>>>(ei);
    wprep_kernel<<<nBlkWp, T>>>(W1, W2);

    // layer 1
    gemm_hmma_kernel<<<nBlkGemm, 256, GEMM_SMEM>>>(x, pBf, nullptr, pH, 0);
    gather_kernel<<<nBlkGath, T>>>(nullptr, pAGG, 0);

    // layer 2
    gemm_hmma_kernel<<<nBlkGemm, 256, GEMM_SMEM>>>(pAGG, pBf + 4608, b1, pH, 1);
    gather_kernel<<<nBlkGath, T>>>(b2, out, 1);
}

// round 8
// speedup vs baseline: 2.6039x; 1.0684x over previous
#include <cuda_runtime.h>
#include <cuda_bf16.h>
#include <cstdint>

#define NNODES 100000
#define NEDGES 800000
#define DH 96
#define C4 (DH / 4)

// ---- scratch ----
__device__ float g_H[NNODES * DH];      // GEMM output pre-scaled: Hs[r] = dis[r]*H[r]
__device__ float g_AGG[NNODES * DH];
__device__ float g_dis[NNODES];
__device__ int   g_cntcur[2 * NNODES];  // [0,N): cnt, [N,2N): cur  (one memset)
__device__ int   g_off[NNODES];         // per-chunk exclusive prefix (bsum NOT applied)
__device__ int   g_bsum[256];           // exclusive chunk sums
__device__ int   g_csr[NEDGES];
// B fragments: [layer][var(hi/lo)][np(2)][kt(6)][nt(6)][lane(32)] -> uint2
__device__ uint2 g_Bfrag[2 * 2 * 2 * 6 * 6 * 32];

#define WPREP_TOTAL (2 * 2 * 2 * 6 * 6 * 32)   // 9216
#define WPREP_BLOCKS ((WPREP_TOTAL + 255) / 256)  // 36
#define HIST_BLOCKS ((NEDGES + 255) / 256)        // 3125
#define GBM 128
#define GEMM_BLOCKS ((NNODES + GBM - 1) / GBM)    // 782

// ============================ helpers ============================

__device__ __forceinline__ uint32_t cvt_bf16x2(float lo, float hi) {
    uint32_t r;
    asm("cvt.rn.satfinite.bf16x2.f32 %0, %1, %2;" : "=r"(r) : "f"(hi), "f"(lo));
    return r;
}

__device__ __forceinline__ void mma_bf16(float* c, const uint32_t* a,
                                         uint32_t b0, uint32_t b1) {
    asm volatile(
        "mma.sync.aligned.m16n8k16.row.col.f32.bf16.bf16.f32 "
        "{%0,%1,%2,%3}, {%4,%5,%6,%7}, {%8,%9}, {%0,%1,%2,%3};"
        : "+f"(c[0]), "+f"(c[1]), "+f"(c[2]), "+f"(c[3])
        : "r"(a[0]), "r"(a[1]), "r"(a[2]), "r"(a[3]), "r"(b0), "r"(b1));
}

// ============================ W fragment body ============================

__device__ __forceinline__ void wprep_body(int idx, const float* __restrict__ W1,
                                           const float* __restrict__ W2) {
    if (idx >= WPREP_TOTAL) return;
    int lane = idx & 31;
    int t = idx >> 5;
    int nt = t % 6;  t /= 6;
    int kt = t % 6;  t /= 6;
    int np = t % 2;  t /= 2;
    int var = t % 2; t /= 2;
    int layer = t;
    const float* W = layer ? W2 : W1;

    int n  = np * 48 + nt * 8 + (lane >> 2);
    int k0 = kt * 16 + (lane & 3) * 2;
    float v[4];
#pragma unroll
    for (int i = 0; i < 4; i++) {
        int k = k0 + (i & 1) + (i >> 1) * 8;
        float w = W[k * DH + n];
        float hi = __bfloat162float(__float2bfloat16(w));
        v[i] = var ? (w - hi) : hi;
    }
    g_Bfrag[idx] = make_uint2(cvt_bf16x2(v[0], v[1]), cvt_bf16x2(v[2], v[3]));
}

// ============================ fused hist + wprep ============================

__global__ void hist_wprep_kernel(const int* __restrict__ ei,
                                  const float* __restrict__ W1,
                                  const float* __restrict__ W2) {
    if (blockIdx.x < WPREP_BLOCKS) {
        wprep_body(blockIdx.x * blockDim.x + threadIdx.x, W1, W2);
    } else {
        int e = (blockIdx.x - WPREP_BLOCKS) * blockDim.x + threadIdx.x;
        if (e < NEDGES) atomicAdd(&g_cntcur[ei[NEDGES + e]], 1);
    }
}

// ============================ scans ============================

#define SCHUNK 512
#define NSBLK ((NNODES + SCHUNK - 1) / SCHUNK)   // 196

__global__ void scan1_kernel() {
    __shared__ int wsum[16];
    const int t = threadIdx.x;
    const int lane = t & 31, warp = t >> 5;
    const int i = blockIdx.x * SCHUNK + t;
    const int v = (i < NNODES) ? g_cntcur[i] : 0;
    int x = v;
#pragma unroll
    for (int o = 1; o < 32; o <<= 1) {
        int y = __shfl_up_sync(0xFFFFFFFF, x, o);
        if (lane >= o) x += y;
    }
    if (lane == 31) wsum[warp] = x;
    __syncthreads();
    if (warp == 0) {
        int s = (lane < 16) ? wsum[lane] : 0;
#pragma unroll
        for (int o = 1; o < 16; o <<= 1) {
            int y = __shfl_up_sync(0xFFFFFFFF, s, o);
            if (lane >= o) s += y;
        }
        if (lane < 16) wsum[lane] = s;
    }
    __syncthreads();
    const int base = (warp > 0) ? wsum[warp - 1] : 0;
    if (i < NNODES) {
        g_off[i] = base + x - v;
        g_dis[i] = rsqrtf((float)v + 1.0f);
    }
    if (t == SCHUNK - 1) g_bsum[blockIdx.x] = base + x;
}

// single-warp exclusive scan of NSBLK(196) chunk totals, 7 per lane
__global__ void scan2_kernel() {
    const int lane = threadIdx.x;
    const int base = lane * 7;
    int v[7], inc[7];
    int tot = 0;
#pragma unroll
    for (int j = 0; j < 7; j++) {
        v[j] = (base + j < NSBLK) ? g_bsum[base + j] : 0;
        tot += v[j];
        inc[j] = tot;
    }
    int x = tot;
#pragma unroll
    for (int o = 1; o < 32; o <<= 1) {
        int y = __shfl_up_sync(0xFFFFFFFF, x, o);
        if (lane >= o) x += y;
    }
    const int excl = x - tot;
#pragma unroll
    for (int j = 0; j < 7; j++)
        if (base + j < NSBLK) g_bsum[base + j] = excl + inc[j] - v[j];
}

// ============================ GEMM body (HMMA) ============================
// Hs[n,96] = dis[n] * (A'[n,96] @ W[96,96]), A' = fuse ? relu(A+bias) : A

#define APITCH 104
#define AROW_BYTES (APITCH * 2)
#define SM_AHI 0
#define SM_ALO (GBM * AROW_BYTES)
#define GEMM_SMEM (2 * GBM * AROW_BYTES)

__device__ __forceinline__ void gemm_body(char* smem, int bid,
                                          const float* __restrict__ A,
                                          const uint2* __restrict__ Bfrag,
                                          const float* __restrict__ bias,
                                          float* __restrict__ H, int fuse) {
    const int tid = threadIdx.x;
    const int lane = tid & 31;
    const int wid = tid >> 5;
    const int wm = wid & 3;
    const int wn = wid >> 2;
    const int row0 = bid * GBM;

    // ---- stage A: load fp32, fuse, split to bf16 hi/lo in smem ----
    {
        const int r = tid >> 1;
        const int cb = (tid & 1) * 48;
        const int grow = row0 + r;
        char* phi = smem + SM_AHI + r * AROW_BYTES;
        char* plo = smem + SM_ALO + r * AROW_BYTES;
#pragma unroll
        for (int q = 0; q < 12; q++) {
            const int k0 = cb + q * 4;
            float4 v;
            if (grow < NNODES) {
                v = *(const float4*)(A + (size_t)grow * DH + k0);
                if (fuse) {
                    const float4 b = *(const float4*)(bias + k0);
                    v.x = fmaxf(v.x + b.x, 0.0f);
                    v.y = fmaxf(v.y + b.y, 0.0f);
                    v.z = fmaxf(v.z + b.z, 0.0f);
                    v.w = fmaxf(v.w + b.w, 0.0f);
                }
            } else {
                v = make_float4(0.f, 0.f, 0.f, 0.f);
            }
            uint32_t h01 = cvt_bf16x2(v.x, v.y);
            uint32_t h23 = cvt_bf16x2(v.z, v.w);
            float lx = v.x - __uint_as_float(h01 << 16);
            float ly = v.y - __uint_as_float(h01 & 0xFFFF0000u);
            float lz = v.z - __uint_as_float(h23 << 16);
            float lw = v.w - __uint_as_float(h23 & 0xFFFF0000u);
            *(uint2*)(phi + k0 * 2) = make_uint2(h01, h23);
            *(uint2*)(plo + k0 * 2) = make_uint2(cvt_bf16x2(lx, ly), cvt_bf16x2(lz, lw));
        }
    }
    __syncthreads();

    float acc[2][6][4];
#pragma unroll
    for (int m = 0; m < 2; m++)
#pragma unroll
        for (int nt = 0; nt < 6; nt++)
#pragma unroll
            for (int i = 0; i < 4; i++) acc[m][nt][i] = 0.0f;

    const int fr = (lane >> 2);
    const int fk = (lane & 3) * 2;

#pragma unroll
    for (int kt = 0; kt < 6; kt++) {
        uint32_t ahi[2][4], alo[2][4];
#pragma unroll
        for (int m = 0; m < 2; m++) {
            const int r = wm * 32 + m * 16 + fr;
            const int kb = (kt * 16 + fk) * 2;
            const char* ph = smem + SM_AHI + r * AROW_BYTES + kb;
            const char* pl = smem + SM_ALO + r * AROW_BYTES + kb;
            ahi[m][0] = *(const uint32_t*)ph;
            ahi[m][1] = *(const uint32_t*)(ph + 8 * AROW_BYTES);
            ahi[m][2] = *(const uint32_t*)(ph + 16);
            ahi[m][3] = *(const uint32_t*)(ph + 8 * AROW_BYTES + 16);
            alo[m][0] = *(const uint32_t*)pl;
            alo[m][1] = *(const uint32_t*)(pl + 8 * AROW_BYTES);
            alo[m][2] = *(const uint32_t*)(pl + 16);
            alo[m][3] = *(const uint32_t*)(pl + 8 * AROW_BYTES + 16);
        }
#pragma unroll
        for (int nt = 0; nt < 6; nt++) {
            const uint2 bhi = Bfrag[(((0 * 2 + wn) * 6 + kt) * 6 + nt) * 32 + lane];
            const uint2 blo = Bfrag[(((1 * 2 + wn) * 6 + kt) * 6 + nt) * 32 + lane];
#pragma unroll
            for (int m = 0; m < 2; m++) {
                mma_bf16(acc[m][nt], ahi[m], bhi.x, bhi.y);
                mma_bf16(acc[m][nt], ahi[m], blo.x, blo.y);
                mma_bf16(acc[m][nt], alo[m], bhi.x, bhi.y);
            }
        }
    }

#pragma unroll
    for (int m = 0; m < 2; m++) {
        const int r = row0 + wm * 32 + m * 16 + fr;
        const float d0 = (r < NNODES) ? g_dis[r] : 0.0f;
        const float d1 = (r + 8 < NNODES) ? g_dis[r + 8] : 0.0f;
#pragma unroll
        for (int nt = 0; nt < 6; nt++) {
            const int col = wn * 48 + nt * 8 + fk;
            if (r < NNODES)
                *(float2*)(H + (size_t)r * DH + col) =
                    make_float2(acc[m][nt][0] * d0, acc[m][nt][1] * d0);
            if (r + 8 < NNODES)
                *(float2*)(H + (size_t)(r + 8) * DH + col) =
                    make_float2(acc[m][nt][2] * d1, acc[m][nt][3] * d1);
        }
    }
}

// ============================ fused fill + gemm1 ============================
// Blocks [0, GEMM_BLOCKS): layer-1 GEMM (needs dis + Bfrag).
// Blocks [GEMM_BLOCKS, +HIST_BLOCKS): CSR slot fill (needs scan2).

__global__ void __launch_bounds__(256)
fill_gemm_kernel(const int* __restrict__ ei, const float* __restrict__ A,
                 const uint2* __restrict__ Bfrag, float* __restrict__ H) {
    extern __shared__ char smem[];
    if (blockIdx.x < GEMM_BLOCKS) {
        gemm_body(smem, blockIdx.x, A, Bfrag, nullptr, H, 0);
    } else {
        int e = (blockIdx.x - GEMM_BLOCKS) * blockDim.x + threadIdx.x;
        if (e < NEDGES) {
            int s = ei[e];
            int d = ei[NEDGES + e];
            int pos = g_off[d] + g_bsum[d >> 9] + atomicAdd(&g_cntcur[NNODES + d], 1);
            g_csr[pos] = s;
        }
    }
}

// standalone layer-2 GEMM
__global__ void __launch_bounds__(256)
gemm_hmma_kernel(const float* __restrict__ A, const uint2* __restrict__ Bfrag,
                 const float* __restrict__ bias, float* __restrict__ H, int fuse) {
    extern __shared__ char smem[];
    gemm_body(smem, blockIdx.x, A, Bfrag, bias, H, fuse);
}

// ============================ gather aggregation ============================
// One warp per node. agg[d] = dis[d] * (Hs[d] + sum_{s in N(d)} Hs[s])

__global__ void __launch_bounds__(256)
gather_kernel(const float* __restrict__ bias, float* __restrict__ out, int mode) {
    int gwid = (blockIdx.x * blockDim.x + threadIdx.x) >> 5;
    int lid = threadIdx.x & 31;
    if (gwid >= NNODES) return;

    const bool active = lid < C4;
    float4 acc = make_float4(0.f, 0.f, 0.f, 0.f);
    if (active)
        acc = __ldg((const float4*)&g_H[(size_t)gwid * DH] + lid);   // self term

    int start = g_off[gwid] + g_bsum[gwid >> 9];
    int deg   = g_cntcur[gwid];
#pragma unroll 4
    for (int i = 0; i < deg; i++) {
        int s = __ldg(&g_csr[start + i]);
        if (active) {
            float4 h = __ldg((const float4*)&g_H[(size_t)s * DH] + lid);
            acc.x += h.x; acc.y += h.y; acc.z += h.z; acc.w += h.w;
        }
    }

    if (active) {
        float dd = g_dis[gwid];
        acc.x *= dd; acc.y *= dd; acc.z *= dd; acc.w *= dd;
        if (mode == 1) {
            float4 b = __ldg((const float4*)bias + lid);
            acc.x = fmaxf(acc.x + b.x, 0.0f);
            acc.y = fmaxf(acc.y + b.y, 0.0f);
            acc.z = fmaxf(acc.z + b.z, 0.0f);
            acc.w = fmaxf(acc.w + b.w, 0.0f);
        }
        ((float4*)(out + (size_t)gwid * DH))[lid] = acc;
    }
}

// ============================ launch ============================

extern "C" void kernel_launch(void* const* d_in, const int* in_sizes, int n_in,
                              void* d_out, int out_size) {
    const float* x  = (const float*)d_in[0];
    const int*   ei = (const int*)d_in[1];
    const float* W1 = (const float*)d_in[2];
    const float* b1 = (const float*)d_in[3];
    const float* W2 = (const float*)d_in[4];
    const float* b2 = (const float*)d_in[5];
    float* out = (float*)d_out;

    void *pH_v, *pAGG_v, *pBf_v, *pCC_v;
    cudaGetSymbolAddress(&pH_v, g_H);
    cudaGetSymbolAddress(&pAGG_v, g_AGG);
    cudaGetSymbolAddress(&pBf_v, g_Bfrag);
    cudaGetSymbolAddress(&pCC_v, g_cntcur);
    float* pH   = (float*)pH_v;
    float* pAGG = (float*)pAGG_v;
    const uint2* pBf = (const uint2*)pBf_v;

    cudaFuncSetAttribute(fill_gemm_kernel,
                         cudaFuncAttributeMaxDynamicSharedMemorySize, GEMM_SMEM);
    cudaFuncSetAttribute(gemm_hmma_kernel,
                         cudaFuncAttributeMaxDynamicSharedMemorySize, GEMM_SMEM);

    const int T = 256;
    int nBlkGath = (NNODES * 32 + T - 1) / T;

    // 1. zero cnt+cur (one memset)
    cudaMemsetAsync(pCC_v, 0, 2 * NNODES * sizeof(int));
    // 2. hist (needs memset) || wprep (independent)
    hist_wprep_kernel<<<WPREP_BLOCKS + HIST_BLOCKS, T>>>(ei, W1, W2);
    // 3. per-chunk scan + dis
    scan1_kernel<<<NSBLK, SCHUNK>>>();
    // 4. chunk-total exclusive scan (single warp)
    scan2_kernel<<<1, 32>>>();
    // 5. fill (needs scan2) || gemm1 (needs dis + Bfrag)
    fill_gemm_kernel<<<GEMM_BLOCKS + HIST_BLOCKS, T, GEMM_SMEM>>>(ei, x, pBf, pH);
    // 6. gather layer 1
    gather_kernel<<<nBlkGath, T>>>(nullptr, pAGG, 0);
    // 7. gemm layer 2
    gemm_hmma_kernel<<<GEMM_BLOCKS, T, GEMM_SMEM>>>(pAGG, pBf + 4608, b1, pH, 1);
    // 8. gather layer 2 (fused bias+relu)
    gather_kernel<<<nBlkGath, T>>>(b2, out, 1);
}